// round 14
// baseline (speedup 1.0000x reference)
#include <cuda_runtime.h>
#include <math.h>
#include <stdint.h>

#define B_  32
#define N_  1024
#define D_  256
#define NEGMASK (-9.0e15f)
#define ALPHA_  0.2f

// ---------------- device scratch ----------------
__device__ float g_z [B_ * N_ * D_];     // z [b][j][d], tf32-RNA-rounded
__device__ float g_s1[B_ * N_];
__device__ float g_s2[B_ * N_];
__device__ float g_m [B_ * N_];
__device__ float g_linv[B_ * N_];
__device__ unsigned g_bits[B_ * N_ * 32];

// ---------------- helpers ----------------
__device__ __forceinline__ uint32_t smem_u32(const void* p) {
    uint32_t a;
    asm("{ .reg .u64 t; cvta.to.shared.u64 t, %1; cvt.u32.u64 %0, t; }" : "=r"(a) : "l"(p));
    return a;
}
__device__ __forceinline__ uint32_t tf32u(float f) {
    uint32_t u; asm("cvt.rna.tf32.f32 %0, %1;" : "=r"(u) : "f"(f));
    return u;
}
__device__ __forceinline__ float tf32f(float f) { return __uint_as_float(tf32u(f)); }

#define CP_ASYNC16(sm, gp) \
    asm volatile("cp.async.cg.shared.global [%0], [%1], 16;" :: "r"(sm), "l"(gp) : "memory")
#define CP_COMMIT()  asm volatile("cp.async.commit_group;" ::: "memory")
#define CP_WAIT0()   asm volatile("cp.async.wait_group 0;" ::: "memory")

__device__ __forceinline__ void mma_tf32(float* c, uint32_t a0, uint32_t a1,
                                         uint32_t a2, uint32_t a3,
                                         uint32_t b0, uint32_t b1) {
    asm volatile(
        "mma.sync.aligned.m16n8k8.row.col.f32.tf32.tf32.f32 "
        "{%0,%1,%2,%3}, {%4,%5,%6,%7}, {%8,%9}, {%0,%1,%2,%3};"
        : "+f"(c[0]), "+f"(c[1]), "+f"(c[2]), "+f"(c[3])
        : "r"(a0), "r"(a1), "r"(a2), "r"(a3), "r"(b0), "r"(b1));
}

// ---------------------------------------------------------------------------
// Kernel 1: z = tf32_rna( h @ W^T + b )  (proven R12)
// ---------------------------------------------------------------------------
__global__ __launch_bounds__(256) void k_zgemm5(const float* __restrict__ h,
                                                const float* __restrict__ W,
                                                const float* __restrict__ bias) {
    __shared__ float As[8][128];
    __shared__ float Bs[8][128];
    const int t  = threadIdx.x;
    const int bm = blockIdx.y;
    const int bn = blockIdx.x;
    const int tr = t >> 4, tc = t & 15;
    const int lm = t >> 1, lx = t & 1;

    const float* hA = h + (size_t)(bm * 128 + lm) * D_ + 4 * lx;
    const float* wB = W + (size_t)(bn * 128 + lm) * D_ + 4 * lx;

    float acc[8][8];
#pragma unroll
    for (int i = 0; i < 8; i++)
#pragma unroll
        for (int j = 0; j < 8; j++) acc[i][j] = 0.f;

    float4 av = *(const float4*)(hA);
    float4 bv = *(const float4*)(wB);

    for (int k0 = 0; k0 < D_; k0 += 8) {
        As[4 * lx + 0][lm] = av.x; As[4 * lx + 1][lm] = av.y;
        As[4 * lx + 2][lm] = av.z; As[4 * lx + 3][lm] = av.w;
        Bs[4 * lx + 0][lm] = bv.x; Bs[4 * lx + 1][lm] = bv.y;
        Bs[4 * lx + 2][lm] = bv.z; Bs[4 * lx + 3][lm] = bv.w;
        __syncthreads();
        if (k0 + 8 < D_) {
            av = *(const float4*)(hA + k0 + 8);
            bv = *(const float4*)(wB + k0 + 8);
        }
#pragma unroll
        for (int k = 0; k < 8; k++) {
            float ra[8], rb[8];
            *(float4*)&ra[0] = *(const float4*)&As[k][4 * tr];
            *(float4*)&ra[4] = *(const float4*)&As[k][64 + 4 * tr];
            *(float4*)&rb[0] = *(const float4*)&Bs[k][4 * tc];
            *(float4*)&rb[4] = *(const float4*)&Bs[k][64 + 4 * tc];
#pragma unroll
            for (int i = 0; i < 8; i++)
#pragma unroll
                for (int j = 0; j < 8; j++) acc[i][j] += ra[i] * rb[j];
        }
        __syncthreads();
    }

    float bcol[8];
#pragma unroll
    for (int j = 0; j < 4; j++) {
        bcol[j]     = bias[bn * 128 + 4 * tc + j];
        bcol[4 + j] = bias[bn * 128 + 64 + 4 * tc + j];
    }
#pragma unroll
    for (int i = 0; i < 8; i++) {
        int r   = (i < 4) ? (4 * tr + i) : (64 + 4 * tr + (i - 4));
        int row = bm * 128 + r;
        float* zp = g_z + (size_t)row * D_ + bn * 128;
        float4 o0 = make_float4(tf32f(acc[i][0] + bcol[0]), tf32f(acc[i][1] + bcol[1]),
                                tf32f(acc[i][2] + bcol[2]), tf32f(acc[i][3] + bcol[3]));
        float4 o1 = make_float4(tf32f(acc[i][4] + bcol[4]), tf32f(acc[i][5] + bcol[5]),
                                tf32f(acc[i][6] + bcol[6]), tf32f(acc[i][7] + bcol[7]));
        *(float4*)(zp + 4 * tc)      = o0;
        *(float4*)(zp + 64 + 4 * tc) = o1;
    }
}

// ---------------------------------------------------------------------------
// Kernel 2: s1 = z . a1, s2 = z . a2 (proven)
// ---------------------------------------------------------------------------
__global__ __launch_bounds__(128) void k_scores(const float* __restrict__ a) {
    int idx  = blockIdx.x * blockDim.x + threadIdx.x;
    int row  = idx >> 5;
    int lane = idx & 31;
    const float* zr = g_z + (size_t)row * D_;
    float a1 = 0.f, a2 = 0.f;
#pragma unroll
    for (int x = 0; x < 8; x++) {
        int d = lane + 32 * x;
        float v = zr[d];
        a1 += v * __ldg(a + d);
        a2 += v * __ldg(a + D_ + d);
    }
#pragma unroll
    for (int o = 16; o > 0; o >>= 1) {
        a1 += __shfl_xor_sync(0xffffffffu, a1, o);
        a2 += __shfl_xor_sync(0xffffffffu, a2, o);
    }
    if (lane == 0) { g_s1[row] = a1; g_s2[row] = a2; }
}

// ---------------------------------------------------------------------------
// Kernel 3: per-row mask stats (proven, 44.9us)
// ---------------------------------------------------------------------------
__global__ __launch_bounds__(256) void k_maskstat2(const int* __restrict__ adj) {
    __shared__ float s2s[N_];
    int row0 = blockIdx.x * 8;
    int b    = row0 >> 10;
    {
        const float4* s = (const float4*)(g_s2 + ((size_t)b << 10));
        ((float4*)s2s)[threadIdx.x] = s[threadIdx.x];
    }
    __syncthreads();
    int w = threadIdx.x >> 5, lane = threadIdx.x & 31;
    int row = row0 + w;
    float s1i = g_s1[row];
    const int* arow = adj + (size_t)row * N_;
    float m = -INFINITY;
    uint32_t word = 0;
#pragma unroll
    for (int k = 0; k < 32; k++) {
        int j = lane + 32 * k;
        bool conn = (arow[j] > 0);
        float x = s1i + s2s[j];
        x = (x >= 0.f) ? x : (ALPHA_ * x);
        uint32_t bal = __ballot_sync(0xffffffffu, conn);
        if (lane == k) word = bal;
        if (conn) m = fmaxf(m, x);
    }
#pragma unroll
    for (int o = 16; o > 0; o >>= 1) m = fmaxf(m, __shfl_xor_sync(0xffffffffu, m, o));
    float l = 0.f;
#pragma unroll
    for (int k = 0; k < 32; k++) {
        uint32_t wk = __shfl_sync(0xffffffffu, word, k);
        if ((wk >> lane) & 1u) {
            float x = s1i + s2s[lane + 32 * k];
            x = (x >= 0.f) ? x : (ALPHA_ * x);
            l += __expf(x - m);
        }
    }
#pragma unroll
    for (int o = 16; o > 0; o >>= 1) l += __shfl_xor_sync(0xffffffffu, l, o);
    g_bits[(size_t)row * 32 + lane] = word;
    if (lane == 0) { g_m[row] = m; g_linv[row] = 1.0f / l; }
}

// ---------------------------------------------------------------------------
// Kernel 4: out = ELU( P @ Z ).  attn8 (proven) + intra-thread pipelining:
// P-gen(c+1) interleaved into mma(c); x2 unrolled loop -> static buffers.
// smem floats: ZS0[32][264] ZS1 | PS0[64][36] PS1 | S2[1024] = 22528 fl
// ---------------------------------------------------------------------------
#define AT_ZS0 0
#define AT_ZS1 8448
#define AT_PS0 16896
#define AT_PS1 19200
#define AT_S2  21504
#define AT_SMF 22528     // 90112 B/CTA, 2 CTAs/SM

// one chunk: mma over ZOFS/POFS; optionally generate next P into PNXT
// between the two k-halves so MUFU/FMUL overlap HMMA/LDS.
template<int ZOFS, int POFS, int PNXT, bool GEN>
__device__ __forceinline__ void do_chunk(const uint32_t* smu, float* sm,
                                         float (&acc)[2][8][4],
                                         int nb, int rb, int pi, int jq,
                                         float s1i, float mi, float linv,
                                         uint32_t wnext, const float* s2n) {
#pragma unroll
    for (int half = 0; half < 2; half++) {
#pragma unroll
        for (int kk = 0; kk < 2; kk++) {
            const int k0 = (half * 2 + kk) * 8;
            uint32_t bf[8][2];
            const int zr0 = ZOFS + (k0)*264 + nb;   // + tq*264 folded below
#pragma unroll
            for (int nt = 0; nt < 8; nt++) {
                // note: tq folded into smu pointer by caller? no -- keep explicit
                bf[nt][0] = 0; bf[nt][1] = 0; // placeholder overwritten below
            }
            (void)zr0;
            // real loads (tq-dependent base computed by caller via nb/rb offsets)
#pragma unroll
            for (int nt = 0; nt < 8; nt++) {
                bf[nt][0] = smu[ZOFS + (k0 + (pi & 0)) * 264 + nb + nt * 8];     // dummy
            }
            // --- replaced below ---
            (void)bf;
            break;
        }
        break;
    }
    // NOTE: function body replaced by macro below (kept single definition site)
}

// The template above is awkward for the tq-dependent addressing; use a macro
// so addresses stay in the caller's register context.
#define MMA_K0(zofs, pofs, k0)                                                  \
    do {                                                                        \
        uint32_t bf[8][2];                                                      \
        const int zr0 = (zofs) + ((k0) + tq) * 264 + nb;                        \
        _Pragma("unroll")                                                       \
        for (int nt = 0; nt < 8; nt++) {                                        \
            bf[nt][0] = smu[zr0 + nt * 8];                                      \
            bf[nt][1] = smu[zr0 + 4 * 264 + nt * 8];                            \
        }                                                                       \
        _Pragma("unroll")                                                       \
        for (int mt = 0; mt < 2; mt++) {                                        \
            int ab = (pofs) + (rb + mt * 16) * 36 + (k0) + tq;                  \
            uint32_t a0 = smu[ab];                                              \
            uint32_t a1 = smu[ab + 8 * 36];                                     \
            uint32_t a2 = smu[ab + 4];                                          \
            uint32_t a3 = smu[ab + 8 * 36 + 4];                                 \
            _Pragma("unroll")                                                   \
            for (int nt = 0; nt < 8; nt++)                                      \
                mma_tf32(acc[mt][nt], a0, a1, a2, a3, bf[nt][0], bf[nt][1]);    \
        }                                                                       \
    } while (0)

#define PGEN(pofs, word, s2c)                                                   \
    do {                                                                        \
        float* prow = sm + (pofs) + pi * 36 + jq * 8;                           \
        _Pragma("unroll")                                                       \
        for (int jj = 0; jj < 8; jj += 2) {                                     \
            float x0 = s1i + (s2c)[jj];                                         \
            float x1 = s1i + (s2c)[jj + 1];                                     \
            x0 = (x0 >= 0.f) ? x0 : (ALPHA_ * x0);                              \
            x1 = (x1 >= 0.f) ? x1 : (ALPHA_ * x1);                              \
            int jl = jq * 8 + jj;                                               \
            float e0 = (((word) >> jl) & 1u) ? x0 : NEGMASK;                    \
            float e1 = (((word) >> (jl + 1)) & 1u) ? x1 : NEGMASK;              \
            float2 p;                                                           \
            p.x = __uint_as_float(tf32u(__expf(e0 - mi) * linv));               \
            p.y = __uint_as_float(tf32u(__expf(e1 - mi) * linv));               \
            *(float2*)(prow + jj) = p;                                          \
        }                                                                       \
    } while (0)

#define ZLOAD(zoff, cn)                                                         \
    do {                                                                        \
        _Pragma("unroll")                                                       \
        for (int q = 0; q < 8; q++) {                                           \
            int idx = t + 256 * q, r = idx >> 6, s = idx & 63;                  \
            CP_ASYNC16(sb + ((zoff) + r * 264) * 4 + s * 16,                    \
                       zbb + (size_t)(32 * (cn) + r) * 1024 + s * 16);          \
        }                                                                       \
        CP_COMMIT();                                                            \
    } while (0)

__global__ __launch_bounds__(256, 2) void k_attn9(const unsigned* __restrict__ bits,
                                                  float* __restrict__ out) {
    extern __shared__ __align__(16) float sm[];
    const uint32_t sb = smem_u32(sm);
    const uint32_t* smu = (const uint32_t*)sm;

    const int t    = threadIdx.x;
    const int lane = t & 31;
    const int wid  = t >> 5;            // 0..7
    const int wr   = wid & 1;
    const int wc   = wid >> 1;
    const int g    = lane >> 2;
    const int tq   = lane & 3;

    const int b  = blockIdx.y;
    const int i0 = blockIdx.x * 64;

    ((float4*)(sm + AT_S2))[t] = ((const float4*)(g_s2 + ((size_t)b << 10)))[t];

    const int pi = t >> 2, jq = t & 3;
    const size_t grow = ((size_t)b << 10) + i0 + pi;
    const float s1i  = g_s1[grow];
    const float mi   = g_m[grow];
    const float linv = g_linv[grow];
    const unsigned* brow = bits + grow * 32;

    const char* zbb = (const char*)(g_z + ((size_t)b << 18));
    const int nb = wc * 64 + g;
    const int rb = wr * 32 + g;

    float acc[2][8][4];
#pragma unroll
    for (int mt = 0; mt < 2; mt++)
#pragma unroll
        for (int nt = 0; nt < 8; nt++)
#pragma unroll
            for (int q = 0; q < 4; q++) acc[mt][nt][q] = 0.f;

    // prologue: Z(0), then P(0) after S2 is visible
    ZLOAD(AT_ZS0, 0);
    __syncthreads();                         // S2 visible
    {
        uint32_t w0 = __ldg(brow + 0);
        const float* s2c = sm + AT_S2 + jq * 8;
        PGEN(AT_PS0, w0, s2c);
    }

#pragma unroll 1
    for (int c = 0; c < 32; c += 2) {
        // ---- even chunk c: buffers ZS0/PS0, gen P(c+1)->PS1
        CP_WAIT0();
        __syncthreads();                     // Z(c), P(c) visible; mma(c-1) done
        ZLOAD(AT_ZS1, c + 1);                // c+1 <= 31 always here
        {
            uint32_t wn = __ldg(brow + c + 1);
            const float* s2n = sm + AT_S2 + (c + 1) * 32 + jq * 8;
            MMA_K0(AT_ZS0, AT_PS0, 0);
            MMA_K0(AT_ZS0, AT_PS0, 8);
            PGEN(AT_PS1, wn, s2n);           // overlaps HMMA of this chunk
            MMA_K0(AT_ZS0, AT_PS0, 16);
            MMA_K0(AT_ZS0, AT_PS0, 24);
        }
        // ---- odd chunk c+1: buffers ZS1/PS1, gen P(c+2)->PS0
        CP_WAIT0();
        __syncthreads();
        if (c + 2 < 32) {
            ZLOAD(AT_ZS0, c + 2);
            uint32_t wn = __ldg(brow + c + 2);
            const float* s2n = sm + AT_S2 + (c + 2) * 32 + jq * 8;
            MMA_K0(AT_ZS1, AT_PS1, 0);
            MMA_K0(AT_ZS1, AT_PS1, 8);
            PGEN(AT_PS0, wn, s2n);
            MMA_K0(AT_ZS1, AT_PS1, 16);
            MMA_K0(AT_ZS1, AT_PS1, 24);
        } else {
            MMA_K0(AT_ZS1, AT_PS1, 0);
            MMA_K0(AT_ZS1, AT_PS1, 8);
            MMA_K0(AT_ZS1, AT_PS1, 16);
            MMA_K0(AT_ZS1, AT_PS1, 24);
        }
    }

    // ---- epilogue: ELU + store
#pragma unroll
    for (int mt = 0; mt < 2; mt++) {
        int row0 = i0 + wr * 32 + mt * 16 + g;
        float* o0 = out + (((size_t)b << 10) + row0) * D_ + wc * 64 + 2 * tq;
        float* o1 = o0 + 8 * D_;
#pragma unroll
        for (int nt = 0; nt < 8; nt++) {
            float v0 = acc[mt][nt][0], v1 = acc[mt][nt][1];
            float v2 = acc[mt][nt][2], v3 = acc[mt][nt][3];
            float2 r0, r1;
            r0.x = (v0 > 0.f) ? v0 : expm1f(v0);
            r0.y = (v1 > 0.f) ? v1 : expm1f(v1);
            r1.x = (v2 > 0.f) ? v2 : expm1f(v2);
            r1.y = (v3 > 0.f) ? v3 : expm1f(v3);
            *(float2*)(o0 + nt * 8) = r0;
            *(float2*)(o1 + nt * 8) = r1;
        }
    }
}

// ---------------------------------------------------------------------------
extern "C" void kernel_launch(void* const* d_in, const int* in_sizes, int n_in,
                              void* d_out, int out_size) {
    const float* h    = (const float*)d_in[0];
    const int*   adj  = (const int*)d_in[1];
    const float* W    = (const float*)d_in[2];
    const float* bias = (const float*)d_in[3];
    const float* a    = (const float*)d_in[4];
    float* out = (float*)d_out;
    (void)in_sizes; (void)n_in; (void)out_size;

    cudaFuncSetAttribute(k_attn9, cudaFuncAttributeMaxDynamicSharedMemorySize,
                         AT_SMF * sizeof(float));

    unsigned* bits_p;
    cudaGetSymbolAddress((void**)&bits_p, g_bits);

    k_zgemm5<<<dim3(2, 256), 256>>>(h, W, bias);
    k_scores<<<(B_ * N_) / 4, 128>>>(a);
    k_maskstat2<<<(B_ * N_) / 8, 256>>>(adj);
    k_attn9<<<dim3(16, 32), 256, AT_SMF * sizeof(float)>>>(bits_p, out);
}

// round 15
// speedup vs baseline: 1.0429x; 1.0429x over previous
#include <cuda_runtime.h>
#include <math.h>
#include <stdint.h>

#define B_  32
#define N_  1024
#define D_  256
#define NEGMASK (-9.0e15f)
#define ALPHA_  0.2f

// ---------------- device scratch ----------------
__device__ float g_z [B_ * N_ * D_];     // z [b][j][d], tf32-RNA-rounded
__device__ float g_s1[B_ * N_];
__device__ float g_s2[B_ * N_];
__device__ float g_s1p[2][B_ * N_];
__device__ float g_s2p[2][B_ * N_];
__device__ float g_m [B_ * N_];
__device__ float g_linv[B_ * N_];
__device__ unsigned g_bits[B_ * N_ * 32];

// ---------------- helpers ----------------
__device__ __forceinline__ uint32_t smem_u32(const void* p) {
    uint32_t a;
    asm("{ .reg .u64 t; cvta.to.shared.u64 t, %1; cvt.u32.u64 %0, t; }" : "=r"(a) : "l"(p));
    return a;
}
__device__ __forceinline__ uint32_t tf32u(float f) {
    uint32_t u; asm("cvt.rna.tf32.f32 %0, %1;" : "=r"(u) : "f"(f));
    return u;
}
__device__ __forceinline__ float tf32f(float f) { return __uint_as_float(tf32u(f)); }

#define CP_ASYNC16(sm, gp) \
    asm volatile("cp.async.cg.shared.global [%0], [%1], 16;" :: "r"(sm), "l"(gp) : "memory")
#define CP_COMMIT()  asm volatile("cp.async.commit_group;" ::: "memory")
#define CP_WAIT0()   asm volatile("cp.async.wait_group 0;" ::: "memory")

__device__ __forceinline__ void mma_tf32(float* c, uint32_t a0, uint32_t a1,
                                         uint32_t a2, uint32_t a3,
                                         uint32_t b0, uint32_t b1) {
    asm volatile(
        "mma.sync.aligned.m16n8k8.row.col.f32.tf32.tf32.f32 "
        "{%0,%1,%2,%3}, {%4,%5,%6,%7}, {%8,%9}, {%0,%1,%2,%3};"
        : "+f"(c[0]), "+f"(c[1]), "+f"(c[2]), "+f"(c[3])
        : "r"(a0), "r"(a1), "r"(a2), "r"(a3), "r"(b0), "r"(b1));
}

// ---------------------------------------------------------------------------
// Kernel 1: z = tf32_rna( h @ W^T + b ) + fused s1/s2 partial dots.
// Mainloop/prefetch proven (R12). Epilogue adds bias into acc, computes
// s1/s2 partials per row, 16-lane shfl reduce, writes g_s?p[bn].
// ---------------------------------------------------------------------------
__global__ __launch_bounds__(256) void k_zgemm6(const float* __restrict__ h,
                                                const float* __restrict__ W,
                                                const float* __restrict__ bias,
                                                const float* __restrict__ av) {
    __shared__ float As[8][128];
    __shared__ float Bs[8][128];
    const int t  = threadIdx.x;
    const int bm = blockIdx.y;
    const int bn = blockIdx.x;
    const int tr = t >> 4, tc = t & 15;
    const int lm = t >> 1, lx = t & 1;

    const float* hA = h + (size_t)(bm * 128 + lm) * D_ + 4 * lx;
    const float* wB = W + (size_t)(bn * 128 + lm) * D_ + 4 * lx;

    float acc[8][8];
#pragma unroll
    for (int i = 0; i < 8; i++)
#pragma unroll
        for (int j = 0; j < 8; j++) acc[i][j] = 0.f;

    float4 avv = *(const float4*)(hA);
    float4 bvv = *(const float4*)(wB);

    for (int k0 = 0; k0 < D_; k0 += 8) {
        As[4 * lx + 0][lm] = avv.x; As[4 * lx + 1][lm] = avv.y;
        As[4 * lx + 2][lm] = avv.z; As[4 * lx + 3][lm] = avv.w;
        Bs[4 * lx + 0][lm] = bvv.x; Bs[4 * lx + 1][lm] = bvv.y;
        Bs[4 * lx + 2][lm] = bvv.z; Bs[4 * lx + 3][lm] = bvv.w;
        __syncthreads();
        if (k0 + 8 < D_) {
            avv = *(const float4*)(hA + k0 + 8);
            bvv = *(const float4*)(wB + k0 + 8);
        }
#pragma unroll
        for (int k = 0; k < 8; k++) {
            float ra[8], rb[8];
            *(float4*)&ra[0] = *(const float4*)&As[k][4 * tr];
            *(float4*)&ra[4] = *(const float4*)&As[k][64 + 4 * tr];
            *(float4*)&rb[0] = *(const float4*)&Bs[k][4 * tc];
            *(float4*)&rb[4] = *(const float4*)&Bs[k][64 + 4 * tc];
#pragma unroll
            for (int i = 0; i < 8; i++)
#pragma unroll
                for (int j = 0; j < 8; j++) acc[i][j] += ra[i] * rb[j];
        }
        __syncthreads();
    }

    // ---- epilogue: bias into acc, s1/s2 partials, tf32 store
    float bcol[8], a1c[8], a2c[8];
#pragma unroll
    for (int j = 0; j < 4; j++) {
        int c0 = bn * 128 + 4 * tc + j;
        int c1 = bn * 128 + 64 + 4 * tc + j;
        bcol[j]     = __ldg(bias + c0);  bcol[4 + j] = __ldg(bias + c1);
        a1c[j]      = __ldg(av + c0);    a1c[4 + j]  = __ldg(av + c1);
        a2c[j]      = __ldg(av + D_ + c0); a2c[4 + j] = __ldg(av + D_ + c1);
    }
    float s1g[8], s2g[8];
#pragma unroll
    for (int i = 0; i < 8; i++) {
        float p1 = 0.f, p2 = 0.f;
#pragma unroll
        for (int j = 0; j < 8; j++) {
            acc[i][j] += bcol[j];
            p1 += acc[i][j] * a1c[j];
            p2 += acc[i][j] * a2c[j];
        }
        s1g[i] = p1; s2g[i] = p2;
    }
#pragma unroll
    for (int o = 1; o <= 8; o <<= 1) {
#pragma unroll
        for (int i = 0; i < 8; i++) {
            s1g[i] += __shfl_xor_sync(0xffffffffu, s1g[i], o);
            s2g[i] += __shfl_xor_sync(0xffffffffu, s2g[i], o);
        }
    }
    if (tc == 0) {
#pragma unroll
        for (int i = 0; i < 8; i++) {
            int r   = (i < 4) ? (4 * tr + i) : (64 + 4 * tr + (i - 4));
            int row = bm * 128 + r;
            g_s1p[bn][row] = s1g[i];
            g_s2p[bn][row] = s2g[i];
        }
    }
#pragma unroll
    for (int i = 0; i < 8; i++) {
        int r   = (i < 4) ? (4 * tr + i) : (64 + 4 * tr + (i - 4));
        int row = bm * 128 + r;
        float* zp = g_z + (size_t)row * D_ + bn * 128;
        float4 o0 = make_float4(tf32f(acc[i][0]), tf32f(acc[i][1]),
                                tf32f(acc[i][2]), tf32f(acc[i][3]));
        float4 o1 = make_float4(tf32f(acc[i][4]), tf32f(acc[i][5]),
                                tf32f(acc[i][6]), tf32f(acc[i][7]));
        *(float4*)(zp + 4 * tc)      = o0;
        *(float4*)(zp + 64 + 4 * tc) = o1;
    }
}

// ---------------------------------------------------------------------------
// Kernel 2: combine the two s1/s2 partials
// ---------------------------------------------------------------------------
__global__ __launch_bounds__(256) void k_combine2() {
    int id = blockIdx.x * 256 + threadIdx.x;
    g_s1[id] = g_s1p[0][id] + g_s1p[1][id];
    g_s2[id] = g_s2p[0][id] + g_s2p[1][id];
}

// ---------------------------------------------------------------------------
// Kernel 3: per-row mask stats v3: int4 adj loads, nibble masks, no ballots.
// Warp per row; thread owns j = 128q + 4*lane + i (q=0..7, i=0..3).
// ---------------------------------------------------------------------------
__global__ __launch_bounds__(256) void k_maskstat3(const int* __restrict__ adj) {
    __shared__ float s2s[N_];
    int row0 = blockIdx.x * 8;
    int b    = row0 >> 10;
    {
        const float4* s = (const float4*)(g_s2 + ((size_t)b << 10));
        ((float4*)s2s)[threadIdx.x] = s[threadIdx.x];
    }
    __syncthreads();
    int w = threadIdx.x >> 5, lane = threadIdx.x & 31;
    int row = row0 + w;
    float s1i = g_s1[row];
    const int4*   arow4 = (const int4*)(adj + (size_t)row * N_);
    const float4* s2s4  = (const float4*)s2s;

    // pass 1: masks + row max
    uint32_t nibs = 0;
    float m = -INFINITY;
#pragma unroll
    for (int q = 0; q < 8; q++) {
        int4   a = __ldg(arow4 + lane + 32 * q);
        float4 s = s2s4[lane + 32 * q];
        float x0 = s1i + s.x; x0 = (x0 >= 0.f) ? x0 : (ALPHA_ * x0);
        float x1 = s1i + s.y; x1 = (x1 >= 0.f) ? x1 : (ALPHA_ * x1);
        float x2 = s1i + s.z; x2 = (x2 >= 0.f) ? x2 : (ALPHA_ * x2);
        float x3 = s1i + s.w; x3 = (x3 >= 0.f) ? x3 : (ALPHA_ * x3);
        uint32_t nib = (a.x > 0 ? 1u : 0u) | (a.y > 0 ? 2u : 0u)
                     | (a.z > 0 ? 4u : 0u) | (a.w > 0 ? 8u : 0u);
        nibs |= nib << (4 * q);
        if (nib & 1u) m = fmaxf(m, x0);
        if (nib & 2u) m = fmaxf(m, x1);
        if (nib & 4u) m = fmaxf(m, x2);
        if (nib & 8u) m = fmaxf(m, x3);
    }
#pragma unroll
    for (int o = 16; o > 0; o >>= 1) m = fmaxf(m, __shfl_xor_sync(0xffffffffu, m, o));

    // pass 2: l = sum of exp over connected (recompute x via LDS.128)
    float l = 0.f;
#pragma unroll
    for (int q = 0; q < 8; q++) {
        float4 s = s2s4[lane + 32 * q];
        uint32_t nib = (nibs >> (4 * q)) & 0xFu;
        float x0 = s1i + s.x; x0 = (x0 >= 0.f) ? x0 : (ALPHA_ * x0);
        float x1 = s1i + s.y; x1 = (x1 >= 0.f) ? x1 : (ALPHA_ * x1);
        float x2 = s1i + s.z; x2 = (x2 >= 0.f) ? x2 : (ALPHA_ * x2);
        float x3 = s1i + s.w; x3 = (x3 >= 0.f) ? x3 : (ALPHA_ * x3);
        if (nib & 1u) l += __expf(x0 - m);
        if (nib & 2u) l += __expf(x1 - m);
        if (nib & 4u) l += __expf(x2 - m);
        if (nib & 8u) l += __expf(x3 - m);
    }
#pragma unroll
    for (int o = 16; o > 0; o >>= 1) l += __shfl_xor_sync(0xffffffffu, l, o);

    // assemble g_bits words: j = 128q+4*lane+i -> word 4q+(lane>>3), bit 4*(lane&7)+i
#pragma unroll
    for (int q = 0; q < 8; q++) {
        uint32_t word = ((nibs >> (4 * q)) & 0xFu) << (4 * (lane & 7));
        word |= __shfl_xor_sync(0xffffffffu, word, 1);
        word |= __shfl_xor_sync(0xffffffffu, word, 2);
        word |= __shfl_xor_sync(0xffffffffu, word, 4);
        if ((lane & 7) == 0)
            g_bits[(size_t)row * 32 + 4 * q + (lane >> 3)] = word;
    }
    if (lane == 0) { g_m[row] = m; g_linv[row] = 1.0f / l; }
}

// ---------------------------------------------------------------------------
// Kernel 4: out = ELU( P @ Z ) -- attn8 verbatim (proven 156.7us)
// ---------------------------------------------------------------------------
#define AT_ZS0 0
#define AT_ZS1 8448
#define AT_PS0 16896
#define AT_PS1 19200
#define AT_S2  21504
#define AT_SMF 22528     // 90112 B/CTA, 2 CTAs/SM

__global__ __launch_bounds__(256, 2) void k_attn8(const unsigned* __restrict__ bits,
                                                  float* __restrict__ out) {
    extern __shared__ __align__(16) float sm[];
    const uint32_t sb = smem_u32(sm);
    const uint32_t* smu = (const uint32_t*)sm;

    const int t    = threadIdx.x;
    const int lane = t & 31;
    const int wid  = t >> 5;
    const int wr   = wid & 1;
    const int wc   = wid >> 1;
    const int g    = lane >> 2;
    const int tq   = lane & 3;

    const int b  = blockIdx.y;
    const int i0 = blockIdx.x * 64;

    ((float4*)(sm + AT_S2))[t] = ((const float4*)(g_s2 + ((size_t)b << 10)))[t];

    const int pi = t >> 2, jq = t & 3;
    const size_t grow = ((size_t)b << 10) + i0 + pi;
    const float s1i  = g_s1[grow];
    const float mi   = g_m[grow];
    const float linv = g_linv[grow];
    const unsigned* brow = bits + grow * 32;

    const char* zbb = (const char*)(g_z + ((size_t)b << 18));

    float acc[2][8][4];
#pragma unroll
    for (int mt = 0; mt < 2; mt++)
#pragma unroll
        for (int nt = 0; nt < 8; nt++)
#pragma unroll
            for (int q = 0; q < 4; q++) acc[mt][nt][q] = 0.f;

#pragma unroll
    for (int q = 0; q < 8; q++) {
        int idx = t + 256 * q, r = idx >> 6, s = idx & 63;
        CP_ASYNC16(sb + (AT_ZS0 + r * 264) * 4 + s * 16,
                   zbb + (size_t)r * 1024 + s * 16);
    }
    CP_COMMIT();
    __syncthreads();

    for (int c = 0; c < 32; c++) {
        {
            uint32_t word = __ldg(brow + c);
            float* prow = sm + ((c & 1) ? AT_PS1 : AT_PS0) + pi * 36 + jq * 8;
            const float* s2c = sm + AT_S2 + c * 32 + jq * 8;
#pragma unroll
            for (int jj = 0; jj < 8; jj += 2) {
                float x0 = s1i + s2c[jj];
                float x1 = s1i + s2c[jj + 1];
                x0 = (x0 >= 0.f) ? x0 : (ALPHA_ * x0);
                x1 = (x1 >= 0.f) ? x1 : (ALPHA_ * x1);
                int jl = jq * 8 + jj;
                float e0 = ((word >> jl) & 1u) ? x0 : NEGMASK;
                float e1 = ((word >> (jl + 1)) & 1u) ? x1 : NEGMASK;
                float2 p;
                p.x = __uint_as_float(tf32u(__expf(e0 - mi) * linv));
                p.y = __uint_as_float(tf32u(__expf(e1 - mi) * linv));
                *(float2*)(prow + jj) = p;
            }
        }
        CP_WAIT0();
        __syncthreads();
        if (c < 31) {
            uint32_t zoff = ((c + 1) & 1) ? AT_ZS1 : AT_ZS0;
#pragma unroll
            for (int q = 0; q < 8; q++) {
                int idx = t + 256 * q, r = idx >> 6, s = idx & 63;
                CP_ASYNC16(sb + (zoff + r * 264) * 4 + s * 16,
                           zbb + (size_t)(32 * (c + 1) + r) * 1024 + s * 16);
            }
            CP_COMMIT();
        }
        {
            const uint32_t zofs = (c & 1) ? AT_ZS1 : AT_ZS0;
            const uint32_t pofs = (c & 1) ? AT_PS1 : AT_PS0;
            const int nb = wc * 64 + g;
            const int rb = wr * 32 + g;
#pragma unroll
            for (int k0 = 0; k0 < 32; k0 += 8) {
                uint32_t bf[8][2];
                const int zr0 = zofs + (k0 + tq) * 264 + nb;
#pragma unroll
                for (int nt = 0; nt < 8; nt++) {
                    bf[nt][0] = smu[zr0 + nt * 8];
                    bf[nt][1] = smu[zr0 + 4 * 264 + nt * 8];
                }
#pragma unroll
                for (int mt = 0; mt < 2; mt++) {
                    int ab = pofs + (rb + mt * 16) * 36 + k0 + tq;
                    uint32_t a0 = smu[ab];
                    uint32_t a1 = smu[ab + 8 * 36];
                    uint32_t a2 = smu[ab + 4];
                    uint32_t a3 = smu[ab + 8 * 36 + 4];
#pragma unroll
                    for (int nt = 0; nt < 8; nt++)
                        mma_tf32(acc[mt][nt], a0, a1, a2, a3, bf[nt][0], bf[nt][1]);
                }
            }
        }
    }

#pragma unroll
    for (int mt = 0; mt < 2; mt++) {
        int row0 = i0 + wr * 32 + mt * 16 + g;
        float* o0 = out + (((size_t)b << 10) + row0) * D_ + wc * 64 + 2 * tq;
        float* o1 = o0 + 8 * D_;
#pragma unroll
        for (int nt = 0; nt < 8; nt++) {
            float v0 = acc[mt][nt][0], v1 = acc[mt][nt][1];
            float v2 = acc[mt][nt][2], v3 = acc[mt][nt][3];
            float2 r0, r1;
            r0.x = (v0 > 0.f) ? v0 : expm1f(v0);
            r0.y = (v1 > 0.f) ? v1 : expm1f(v1);
            r1.x = (v2 > 0.f) ? v2 : expm1f(v2);
            r1.y = (v3 > 0.f) ? v3 : expm1f(v3);
            *(float2*)(o0 + nt * 8) = r0;
            *(float2*)(o1 + nt * 8) = r1;
        }
    }
}

// ---------------------------------------------------------------------------
extern "C" void kernel_launch(void* const* d_in, const int* in_sizes, int n_in,
                              void* d_out, int out_size) {
    const float* h    = (const float*)d_in[0];
    const int*   adj  = (const int*)d_in[1];
    const float* W    = (const float*)d_in[2];
    const float* bias = (const float*)d_in[3];
    const float* a    = (const float*)d_in[4];
    float* out = (float*)d_out;
    (void)in_sizes; (void)n_in; (void)out_size;

    cudaFuncSetAttribute(k_attn8, cudaFuncAttributeMaxDynamicSharedMemorySize,
                         AT_SMF * sizeof(float));

    unsigned* bits_p;
    cudaGetSymbolAddress((void**)&bits_p, g_bits);

    k_zgemm6<<<dim3(2, 256), 256>>>(h, W, bias, a);
    k_combine2<<<128, 256>>>();
    k_maskstat3<<<(B_ * N_) / 8, 256>>>(adj);
    k_attn8<<<dim3(16, 32), 256, AT_SMF * sizeof(float)>>>(bits_p, out);
}